// round 2
// baseline (speedup 1.0000x reference)
#include <cuda_runtime.h>
#include <cuda_bf16.h>
#include <math.h>

#define BB 256
#define LL 200
#define DD 512

// ---------------- scratch (static device globals; no allocation) ----------------
__device__ float g_xproj[(size_t)LL * BB * 3 * DD];   // [L,B,3D] GRU input proj (+bih)
__device__ float g_sseq [(size_t)LL * BB * DD];       // [L,B,D] GRU outputs
__device__ float g_rx   [(size_t)LL * BB * DD];       // AUGRU x-projections (+bias)
__device__ float g_ux   [(size_t)LL * BB * DD];
__device__ float g_nx   [(size_t)LL * BB * DD];
__device__ float g_u    [BB * DD];                    // u[b,:] = w @ target[b]
__device__ float g_logits[LL * BB];
__device__ float g_att   [LL * BB];
__device__ float g_r     [BB * DD];
__device__ float g_ueff  [BB * DD];
__device__ float g_h     [2 * BB * DD];               // AUGRU ping-pong
__device__ float g_zero  [BB * DD];

__device__ __forceinline__ float sigmoidf_(float x) {
    return 1.0f / (1.0f + __expf(-x));
}

// ---------------- generic NT SGEMM: C[m,n] = sum_k A[m,k] * W[n*ldw+woff+k] (+bias[n]) ----
// K = DD fixed. Tiles 64x64x16, 256 threads, 4x4 per thread. All dims multiples of tile.
// remap=1: A row m = b*LL + l  ->  output row l*BB + b   (for x_proj layout [L,B,*])
__global__ void sgemm_nt(const float* __restrict__ A, int lda,
                         const float* __restrict__ W, int ldw, int woff,
                         const float* __restrict__ bias,
                         float* __restrict__ C, int ldc, int remap)
{
    __shared__ float As[16][64];
    __shared__ float Ws[16][64];
    const int bm = blockIdx.x * 64;
    const int bn = blockIdx.y * 64;
    const int tid = threadIdx.x;
    const int tx = tid & 15;       // n dir
    const int ty = tid >> 4;       // m dir
    const int lrow = tid >> 2;     // 0..63
    const int lc4  = (tid & 3) * 4;

    float acc[4][4];
    #pragma unroll
    for (int i = 0; i < 4; i++)
        #pragma unroll
        for (int j = 0; j < 4; j++) acc[i][j] = 0.f;

    const float* Ap = A + (size_t)(bm + lrow) * lda + lc4;
    const float* Wp = W + (size_t)(bn + lrow) * ldw + woff + lc4;

    for (int k0 = 0; k0 < DD; k0 += 16) {
        float4 av = *(const float4*)(Ap + k0);
        float4 wv = *(const float4*)(Wp + k0);
        As[lc4 + 0][lrow] = av.x; As[lc4 + 1][lrow] = av.y;
        As[lc4 + 2][lrow] = av.z; As[lc4 + 3][lrow] = av.w;
        Ws[lc4 + 0][lrow] = wv.x; Ws[lc4 + 1][lrow] = wv.y;
        Ws[lc4 + 2][lrow] = wv.z; Ws[lc4 + 3][lrow] = wv.w;
        __syncthreads();
        #pragma unroll
        for (int k = 0; k < 16; k++) {
            float4 a = *(const float4*)&As[k][ty * 4];
            float4 w = *(const float4*)&Ws[k][tx * 4];
            float ar[4] = {a.x, a.y, a.z, a.w};
            float wr[4] = {w.x, w.y, w.z, w.w};
            #pragma unroll
            for (int i = 0; i < 4; i++)
                #pragma unroll
                for (int j = 0; j < 4; j++) acc[i][j] += ar[i] * wr[j];
        }
        __syncthreads();
    }

    float bv[4] = {0.f, 0.f, 0.f, 0.f};
    if (bias) {
        float4 b4 = *(const float4*)(bias + bn + tx * 4);
        bv[0] = b4.x; bv[1] = b4.y; bv[2] = b4.z; bv[3] = b4.w;
    }
    #pragma unroll
    for (int i = 0; i < 4; i++) {
        int gm = bm + ty * 4 + i;
        int orow = remap ? (gm % LL) * BB + gm / LL : gm;
        float4 o;
        o.x = acc[i][0] + bv[0]; o.y = acc[i][1] + bv[1];
        o.z = acc[i][2] + bv[2]; o.w = acc[i][3] + bv[3];
        *(float4*)(C + (size_t)orow * ldc + bn + tx * 4) = o;
    }
}

// ---------------- GRU step: hp = h@Whh^T (3 gates), gate, write s_seq[l] ----------------
// grid (BB/32, DD/32), 256 threads, 2x2 per thread per gate.
__global__ void gru_step(const float* __restrict__ hprev,   // [BB,DD]
                         const float* __restrict__ Whh,     // [3DD,DD]
                         const float* __restrict__ bhh,     // [3DD]
                         const float* __restrict__ xp,      // x_proj + l*BB*3DD  [BB,3DD]
                         float* __restrict__ hout)          // s_seq + l*BB*DD
{
    __shared__ float As[32][33];
    __shared__ float Ws[3][32][33];
    const int bm = blockIdx.x * 32;   // b
    const int bn = blockIdx.y * 32;   // d
    const int tid = threadIdx.x;
    const int tx = tid & 15, ty = tid >> 4;
    const int lrow = tid >> 3;        // 0..31
    const int lc4  = (tid & 7) * 4;   // 0..28

    float acc[3][2][2];
    #pragma unroll
    for (int g = 0; g < 3; g++)
        #pragma unroll
        for (int i = 0; i < 2; i++)
            #pragma unroll
            for (int j = 0; j < 2; j++) acc[g][i][j] = 0.f;

    for (int k0 = 0; k0 < DD; k0 += 32) {
        float4 av = *(const float4*)(hprev + (size_t)(bm + lrow) * DD + k0 + lc4);
        As[lc4 + 0][lrow] = av.x; As[lc4 + 1][lrow] = av.y;
        As[lc4 + 2][lrow] = av.z; As[lc4 + 3][lrow] = av.w;
        #pragma unroll
        for (int g = 0; g < 3; g++) {
            float4 wv = *(const float4*)(Whh + (size_t)(g * DD + bn + lrow) * DD + k0 + lc4);
            Ws[g][lc4 + 0][lrow] = wv.x; Ws[g][lc4 + 1][lrow] = wv.y;
            Ws[g][lc4 + 2][lrow] = wv.z; Ws[g][lc4 + 3][lrow] = wv.w;
        }
        __syncthreads();
        #pragma unroll
        for (int k = 0; k < 32; k++) {
            float a0 = As[k][ty * 2 + 0];
            float a1 = As[k][ty * 2 + 1];
            #pragma unroll
            for (int g = 0; g < 3; g++) {
                float w0 = Ws[g][k][tx * 2 + 0];
                float w1 = Ws[g][k][tx * 2 + 1];
                acc[g][0][0] += a0 * w0; acc[g][0][1] += a0 * w1;
                acc[g][1][0] += a1 * w0; acc[g][1][1] += a1 * w1;
            }
        }
        __syncthreads();
    }

    #pragma unroll
    for (int i = 0; i < 2; i++) {
        #pragma unroll
        for (int j = 0; j < 2; j++) {
            int b = bm + ty * 2 + i;
            int n = bn + tx * 2 + j;
            const float* xr = xp + (size_t)b * 3 * DD;
            float hr = acc[0][i][j] + bhh[n];
            float hz = acc[1][i][j] + bhh[DD + n];
            float hn = acc[2][i][j] + bhh[2 * DD + n];
            float r = sigmoidf_(xr[n] + hr);
            float z = sigmoidf_(xr[DD + n] + hz);
            float nn = tanhf(xr[2 * DD + n] + r * hn);
            float hp = hprev[(size_t)b * DD + n];
            hout[(size_t)b * DD + n] = (1.f - z) * nn + z * hp;
        }
    }
}

// ---------------- AUGRU phase A: r and u_eff ----------------
__global__ void augru_a(const float* __restrict__ h,     // [BB,DD]
                        const float* __restrict__ Wr,    // reset_w [DD,2DD], h-half cols 0..DD
                        const float* __restrict__ Wu,    // update_w
                        const float* __restrict__ rx,    // +l*BB*DD (incl bias)
                        const float* __restrict__ ux,
                        const float* __restrict__ att_l, // +l*BB
                        float* __restrict__ rbuf,
                        float* __restrict__ uebuf)
{
    __shared__ float As[32][33];
    __shared__ float Ws[2][32][33];
    const int bm = blockIdx.x * 32;
    const int bn = blockIdx.y * 32;
    const int tid = threadIdx.x;
    const int tx = tid & 15, ty = tid >> 4;
    const int lrow = tid >> 3;
    const int lc4  = (tid & 7) * 4;

    float acc[2][2][2];
    #pragma unroll
    for (int g = 0; g < 2; g++)
        #pragma unroll
        for (int i = 0; i < 2; i++)
            #pragma unroll
            for (int j = 0; j < 2; j++) acc[g][i][j] = 0.f;

    for (int k0 = 0; k0 < DD; k0 += 32) {
        float4 av = *(const float4*)(h + (size_t)(bm + lrow) * DD + k0 + lc4);
        As[lc4 + 0][lrow] = av.x; As[lc4 + 1][lrow] = av.y;
        As[lc4 + 2][lrow] = av.z; As[lc4 + 3][lrow] = av.w;
        {
            float4 wv = *(const float4*)(Wr + (size_t)(bn + lrow) * (2 * DD) + k0 + lc4);
            Ws[0][lc4 + 0][lrow] = wv.x; Ws[0][lc4 + 1][lrow] = wv.y;
            Ws[0][lc4 + 2][lrow] = wv.z; Ws[0][lc4 + 3][lrow] = wv.w;
        }
        {
            float4 wv = *(const float4*)(Wu + (size_t)(bn + lrow) * (2 * DD) + k0 + lc4);
            Ws[1][lc4 + 0][lrow] = wv.x; Ws[1][lc4 + 1][lrow] = wv.y;
            Ws[1][lc4 + 2][lrow] = wv.z; Ws[1][lc4 + 3][lrow] = wv.w;
        }
        __syncthreads();
        #pragma unroll
        for (int k = 0; k < 32; k++) {
            float a0 = As[k][ty * 2 + 0];
            float a1 = As[k][ty * 2 + 1];
            #pragma unroll
            for (int g = 0; g < 2; g++) {
                float w0 = Ws[g][k][tx * 2 + 0];
                float w1 = Ws[g][k][tx * 2 + 1];
                acc[g][0][0] += a0 * w0; acc[g][0][1] += a0 * w1;
                acc[g][1][0] += a1 * w0; acc[g][1][1] += a1 * w1;
            }
        }
        __syncthreads();
    }

    #pragma unroll
    for (int i = 0; i < 2; i++) {
        #pragma unroll
        for (int j = 0; j < 2; j++) {
            int b = bm + ty * 2 + i;
            int n = bn + tx * 2 + j;
            size_t idx = (size_t)b * DD + n;
            float r = sigmoidf_(acc[0][i][j] + rx[idx]);
            float u = sigmoidf_(acc[1][i][j] + ux[idx]);
            rbuf[idx]  = r;
            uebuf[idx] = att_l[b] * u;
        }
    }
}

// ---------------- AUGRU phase B: hh = tanh((h*r)@Wh^T + nx), h' = (1-ue)h + ue*hh ----------
__global__ void augru_b(const float* __restrict__ h,
                        const float* __restrict__ rbuf,
                        const float* __restrict__ Wh,    // hhat_w [DD,2DD]
                        const float* __restrict__ nx,    // +l*BB*DD (incl bias)
                        const float* __restrict__ uebuf,
                        float* __restrict__ hout)
{
    __shared__ float As[32][33];
    __shared__ float Ws[32][33];
    const int bm = blockIdx.x * 32;
    const int bn = blockIdx.y * 32;
    const int tid = threadIdx.x;
    const int tx = tid & 15, ty = tid >> 4;
    const int lrow = tid >> 3;
    const int lc4  = (tid & 7) * 4;

    float acc[2][2];
    acc[0][0] = acc[0][1] = acc[1][0] = acc[1][1] = 0.f;

    for (int k0 = 0; k0 < DD; k0 += 32) {
        size_t aidx = (size_t)(bm + lrow) * DD + k0 + lc4;
        float4 av = *(const float4*)(h + aidx);
        float4 rv = *(const float4*)(rbuf + aidx);
        As[lc4 + 0][lrow] = av.x * rv.x; As[lc4 + 1][lrow] = av.y * rv.y;
        As[lc4 + 2][lrow] = av.z * rv.z; As[lc4 + 3][lrow] = av.w * rv.w;
        float4 wv = *(const float4*)(Wh + (size_t)(bn + lrow) * (2 * DD) + k0 + lc4);
        Ws[lc4 + 0][lrow] = wv.x; Ws[lc4 + 1][lrow] = wv.y;
        Ws[lc4 + 2][lrow] = wv.z; Ws[lc4 + 3][lrow] = wv.w;
        __syncthreads();
        #pragma unroll
        for (int k = 0; k < 32; k++) {
            float a0 = As[k][ty * 2 + 0];
            float a1 = As[k][ty * 2 + 1];
            float w0 = Ws[k][tx * 2 + 0];
            float w1 = Ws[k][tx * 2 + 1];
            acc[0][0] += a0 * w0; acc[0][1] += a0 * w1;
            acc[1][0] += a1 * w0; acc[1][1] += a1 * w1;
        }
        __syncthreads();
    }

    #pragma unroll
    for (int i = 0; i < 2; i++) {
        #pragma unroll
        for (int j = 0; j < 2; j++) {
            int b = bm + ty * 2 + i;
            int n = bn + tx * 2 + j;
            size_t idx = (size_t)b * DD + n;
            float hh = tanhf(acc[i][j] + nx[idx]);
            float ue = uebuf[idx];
            hout[idx] = (1.f - ue) * h[idx] + ue * hh;
        }
    }
}

// ---------------- attention ----------------
__global__ void attn_logits(const float* __restrict__ s,   // s_seq [L,B,D]
                            const float* __restrict__ u,   // [B,D]
                            float* __restrict__ logits)    // [L,B]
{
    int gw = (blockIdx.x * blockDim.x + threadIdx.x) >> 5;   // row = l*BB+b
    int lane = threadIdx.x & 31;
    int b = gw & (BB - 1);
    const float4* sr = (const float4*)(s + (size_t)gw * DD);
    const float4* ur = (const float4*)(u + (size_t)b * DD);
    float acc = 0.f;
    #pragma unroll
    for (int k = lane; k < DD / 4; k += 32) {
        float4 a = sr[k], c = ur[k];
        acc += a.x * c.x + a.y * c.y + a.z * c.z + a.w * c.w;
    }
    #pragma unroll
    for (int o = 16; o > 0; o >>= 1) acc += __shfl_xor_sync(0xffffffffu, acc, o);
    if (lane == 0) logits[gw] = acc;
}

__global__ void attn_softmax(const float* __restrict__ logits, float* __restrict__ att)
{
    int b = blockIdx.x, t = threadIdx.x;
    __shared__ float red[256];
    float v = (t < LL) ? logits[t * BB + b] : -1e30f;
    red[t] = v;
    __syncthreads();
    for (int s = 128; s > 0; s >>= 1) {
        if (t < s) red[t] = fmaxf(red[t], red[t + s]);
        __syncthreads();
    }
    float mx = red[0];
    __syncthreads();
    float e = (t < LL) ? expf(v - mx) : 0.f;
    red[t] = e;
    __syncthreads();
    for (int s = 128; s > 0; s >>= 1) {
        if (t < s) red[t] += red[t + s];
        __syncthreads();
    }
    float inv = 1.f / red[0];
    if (t < LL) att[t * BB + b] = e * inv;
}

__global__ void zero_kernel(float* __restrict__ p, int n)
{
    int i = blockIdx.x * blockDim.x + threadIdx.x;
    if (i < n) p[i] = 0.f;
}

// ---------------- host ----------------
extern "C" void kernel_launch(void* const* d_in, const int* in_sizes, int n_in,
                              void* d_out, int out_size)
{
    const float* session  = (const float*)d_in[0];
    const float* target   = (const float*)d_in[1];
    const float* w        = (const float*)d_in[2];
    const float* wih      = (const float*)d_in[3];
    const float* whh      = (const float*)d_in[4];
    const float* bih      = (const float*)d_in[5];
    const float* bhh      = (const float*)d_in[6];
    const float* reset_w  = (const float*)d_in[7];
    const float* reset_b  = (const float*)d_in[8];
    const float* update_w = (const float*)d_in[9];
    const float* update_b = (const float*)d_in[10];
    const float* hhat_w   = (const float*)d_in[11];
    const float* hhat_b   = (const float*)d_in[12];
    float* out = (float*)d_out;

    float *xproj, *sseq, *rx, *ux, *nx, *u, *logits, *att, *rbuf, *uebuf, *hb, *zero;
    cudaGetSymbolAddress((void**)&xproj, g_xproj);
    cudaGetSymbolAddress((void**)&sseq,  g_sseq);
    cudaGetSymbolAddress((void**)&rx,    g_rx);
    cudaGetSymbolAddress((void**)&ux,    g_ux);
    cudaGetSymbolAddress((void**)&nx,    g_nx);
    cudaGetSymbolAddress((void**)&u,     g_u);
    cudaGetSymbolAddress((void**)&logits,g_logits);
    cudaGetSymbolAddress((void**)&att,   g_att);
    cudaGetSymbolAddress((void**)&rbuf,  g_r);
    cudaGetSymbolAddress((void**)&uebuf, g_ueff);
    cudaGetSymbolAddress((void**)&hb,    g_h);
    cudaGetSymbolAddress((void**)&zero,  g_zero);

    zero_kernel<<<(BB * DD + 255) / 256, 256>>>(zero, BB * DD);

    // 1) x_proj = session @ Wih^T + bih   -> [L,B,3D]
    {
        dim3 g(BB * LL / 64, 3 * DD / 64);
        sgemm_nt<<<g, 256>>>(session, DD, wih, DD, 0, bih, xproj, 3 * DD, 1);
    }

    // 2) GRU recurrence; s_seq holds h history (h0 = 0)
    {
        dim3 g(BB / 32, DD / 32);
        for (int l = 0; l < LL; l++) {
            const float* hp = (l == 0) ? zero : sseq + (size_t)(l - 1) * BB * DD;
            gru_step<<<g, 256>>>(hp, whh, bhh,
                                 xproj + (size_t)l * BB * 3 * DD,
                                 sseq + (size_t)l * BB * DD);
        }
    }

    // 3) u[b,:] = w @ target[b]   (NT: C[b,d] = sum_e target[b,e]*w[d,e])
    {
        dim3 g(BB / 64, DD / 64);
        sgemm_nt<<<g, 256>>>(target, DD, w, DD, 0, nullptr, u, DD, 0);
    }

    // 4) AUGRU x-projections (x = s_seq), biases folded in
    {
        dim3 g(BB * LL / 64, DD / 64);
        sgemm_nt<<<g, 256>>>(sseq, DD, reset_w,  2 * DD, DD, reset_b,  rx, DD, 0);
        sgemm_nt<<<g, 256>>>(sseq, DD, update_w, 2 * DD, DD, update_b, ux, DD, 0);
        sgemm_nt<<<g, 256>>>(sseq, DD, hhat_w,   2 * DD, DD, hhat_b,   nx, DD, 0);
    }

    // 5) attention
    attn_logits<<<LL * BB / 8, 256>>>(sseq, u, logits);
    attn_softmax<<<BB, 256>>>(logits, att);

    // 6) AUGRU recurrence; init h = s_seq[L-1]; last step writes d_out
    {
        dim3 g(BB / 32, DD / 32);
        for (int l = 0; l < LL; l++) {
            const float* hc = (l == 0) ? sseq + (size_t)(LL - 1) * BB * DD
                                       : hb + (size_t)(l & 1) * BB * DD;
            float* ho = (l == LL - 1) ? out : hb + (size_t)((l + 1) & 1) * BB * DD;
            augru_a<<<g, 256>>>(hc, reset_w, update_w,
                                rx + (size_t)l * BB * DD,
                                ux + (size_t)l * BB * DD,
                                att + l * BB, rbuf, uebuf);
            augru_b<<<g, 256>>>(hc, rbuf, hhat_w,
                                nx + (size_t)l * BB * DD, uebuf, ho);
        }
    }
}